// round 16
// baseline (speedup 1.0000x reference)
#include <cuda_runtime.h>
#include <cuda_bf16.h>
#include <stdint.h>
#include <math.h>

#define D_MODEL 256
#define D_FF    1024
#define T_      2048
#define B_      4
#define BT      8192
#define RMS_EPS 1e-5f
#define LOG2E   1.4426950408889634f

typedef __nv_bfloat16 bf16;

// -------------------- scratch (no allocs allowed) --------------------
__device__ bf16  g_w16[1048576];
__device__ bf16  g_h16[BT * D_MODEL];
__device__ bf16  g_q16[BT * D_MODEL];    // pre-scaled by 0.125*log2e
__device__ bf16  g_k16[BT * D_MODEL];
__device__ bf16  g_vt16[BT * D_MODEL];   // v transposed: [(b*4+h)*64+d][t]
__device__ bf16  g_attn16[BT * D_MODEL];
__device__ bf16  g_silu16[BT * D_FF];
__device__ float g_x1[BT * D_MODEL];

// -------------------- helpers --------------------
__device__ __forceinline__ uint32_t pkbf(float lo, float hi) {
    uint32_t r;
    asm("cvt.rn.bf16x2.f32 %0,%1,%2;" : "=r"(r) : "f"(hi), "f"(lo));
    return r;
}
__device__ __forceinline__ float ex2(float x) {
    float y;
    asm("ex2.approx.f32 %0,%1;" : "=f"(y) : "f"(x));
    return y;
}
__device__ __forceinline__ void mma16(float* d, uint32_t a0, uint32_t a1, uint32_t a2,
                                      uint32_t a3, uint32_t b0, uint32_t b1) {
    asm volatile(
        "mma.sync.aligned.m16n8k16.row.col.f32.bf16.bf16.f32 "
        "{%0,%1,%2,%3},{%4,%5,%6,%7},{%8,%9},{%0,%1,%2,%3};"
        : "+f"(d[0]), "+f"(d[1]), "+f"(d[2]), "+f"(d[3])
        : "r"(a0), "r"(a1), "r"(a2), "r"(a3), "r"(b0), "r"(b1));
}
__device__ __forceinline__ void ldsm4(uint32_t& r0, uint32_t& r1, uint32_t& r2,
                                      uint32_t& r3, uint32_t addr) {
    asm volatile("ldmatrix.sync.aligned.m8n8.x4.shared.b16 {%0,%1,%2,%3},[%4];"
                 : "=r"(r0), "=r"(r1), "=r"(r2), "=r"(r3) : "r"(addr));
}
__device__ __forceinline__ uint32_t s2u(const void* p) {
    return (uint32_t)__cvta_generic_to_shared(p);
}
__device__ __forceinline__ void cp16(uint32_t s, const void* g) {
    asm volatile("cp.async.cg.shared.global [%0],[%1],16;" :: "r"(s), "l"(g) : "memory");
}
#define CP_COMMIT asm volatile("cp.async.commit_group;" ::: "memory")
#define CP_WAIT0  asm volatile("cp.async.wait_group 0;" ::: "memory")
#define CP_WAIT1  asm volatile("cp.async.wait_group 1;" ::: "memory")

// -------------------- weight fp32 -> bf16 --------------------
__global__ void cvtw_kernel(const float* __restrict__ wq, const float* __restrict__ wk,
                            const float* __restrict__ wv, const float* __restrict__ wo,
                            const float* __restrict__ wg, const float* __restrict__ wu,
                            const float* __restrict__ wd) {
    const float* src; int n, off;
    switch (blockIdx.y) {
        case 0: src = wq; n = 65536;  off = 0;      break;
        case 1: src = wk; n = 65536;  off = 65536;  break;
        case 2: src = wv; n = 65536;  off = 131072; break;
        case 3: src = wo; n = 65536;  off = 196608; break;
        case 4: src = wg; n = 262144; off = 262144; break;
        case 5: src = wu; n = 262144; off = 524288; break;
        default: src = wd; n = 262144; off = 786432; break;
    }
    const int i = (blockIdx.x * 256 + threadIdx.x) * 4;
    if (i < n) {
        const float4 v = *(const float4*)(src + i);
        uint2 u = make_uint2(pkbf(v.x, v.y), pkbf(v.z, v.w));
        *(uint2*)&g_w16[off + i] = u;
    }
}

// -------------------- rmsnorm -> bf16 into g_h16 --------------------
__global__ void rmsnorm_kernel(const float* __restrict__ x, const float* __restrict__ w) {
    const int row = blockIdx.x;
    const int tid = threadIdx.x;
    const float v = x[(size_t)row * D_MODEL + tid];
    float ss = v * v;
#pragma unroll
    for (int m = 16; m; m >>= 1) ss += __shfl_xor_sync(0xffffffffu, ss, m);
    __shared__ float ws[8];
    __shared__ float s_tot;
    if ((tid & 31) == 0) ws[tid >> 5] = ss;
    __syncthreads();
    if (tid < 8) {
        float t = ws[tid];
        t += __shfl_xor_sync(0xffu, t, 4);
        t += __shfl_xor_sync(0xffu, t, 2);
        t += __shfl_xor_sync(0xffu, t, 1);
        if (tid == 0) s_tot = t;
    }
    __syncthreads();
    const float r = rsqrtf(s_tot * (1.0f / D_MODEL) + RMS_EPS);
    g_h16[(size_t)row * D_MODEL + tid] = __float2bfloat16(v * r * w[tid]);
}

// -------------------- bf16 GEMM core v2: BM=64 BN=128 BK=32, 128 thr ---------
__device__ __forceinline__ void gemm_core2(const bf16* __restrict__ A,
                                           const bf16* __restrict__ W,
                                           int K, uint32_t* As, uint32_t* Bs,
                                           float (&acc)[2][8][4]) {
    const int tid = threadIdx.x, lane = tid & 31, w = tid >> 5;
    const int m4 = lane >> 3, r8 = lane & 7;
    const int bm = blockIdx.x * 64, bn = blockIdx.y * 128;
    const int wm = (w & 1) * 32, wn = (w >> 1) * 64;

#pragma unroll
    for (int mt = 0; mt < 2; mt++)
#pragma unroll
        for (int nt = 0; nt < 8; nt++)
#pragma unroll
            for (int j = 0; j < 4; j++) acc[mt][nt][j] = 0.f;

    const bf16* gap[2];
    uint32_t aoff[2];
#pragma unroll
    for (int i = 0; i < 2; ++i) {
        const int idx = tid + i * 128, r = idx >> 2, c = idx & 3;
        gap[i] = A + (size_t)(bm + r) * K + c * 8;
        aoff[i] = ((r * 16 + ((c ^ ((r >> 1) & 3)) << 2)) << 2);
    }
    const bf16* gbp[4];
    uint32_t boff[4];
#pragma unroll
    for (int i = 0; i < 4; ++i) {
        const int idx = tid + i * 128, r = idx >> 2, c = idx & 3;
        gbp[i] = W + (size_t)(bn + r) * K + c * 8;
        boff[i] = ((r * 16 + ((c ^ ((r >> 1) & 3)) << 2)) << 2);
    }
    const uint32_t asb = s2u(As), bsb = s2u(Bs);

    const int khalf = m4 >> 1;
    int rowA[2], swA[2], rowB[4], swB[4];
#pragma unroll
    for (int mt = 0; mt < 2; ++mt) {
        const int R = wm + mt * 16 + (m4 & 1) * 8 + r8;
        rowA[mt] = R * 64;
        swA[mt] = (R >> 1) & 3;
    }
#pragma unroll
    for (int g = 0; g < 4; ++g) {
        const int R = wn + (2 * g + (m4 & 1)) * 8 + r8;
        rowB[g] = R * 64;
        swB[g] = (R >> 1) & 3;
    }

    const int NK = K >> 5;
#pragma unroll
    for (int i = 0; i < 2; ++i) cp16(asb + aoff[i], gap[i]);
#pragma unroll
    for (int i = 0; i < 4; ++i) cp16(bsb + boff[i], gbp[i]);
    CP_COMMIT;
    if (NK > 1) {
#pragma unroll
        for (int i = 0; i < 2; ++i) cp16(asb + 4096 + aoff[i], gap[i] + 32);
#pragma unroll
        for (int i = 0; i < 4; ++i) cp16(bsb + 8192 + boff[i], gbp[i] + 32);
    }
    CP_COMMIT;

    for (int it = 0; it < NK; ++it) {
        CP_WAIT1;
        __syncthreads();
        if (it + 2 < NK) {
            const int st = (it + 2) % 3;
            const int ko = (it + 2) << 5;
#pragma unroll
            for (int i = 0; i < 2; ++i) cp16(asb + st * 4096 + aoff[i], gap[i] + ko);
#pragma unroll
            for (int i = 0; i < 4; ++i) cp16(bsb + st * 8192 + boff[i], gbp[i] + ko);
        }
        CP_COMMIT;
        const uint32_t Ab = asb + (it % 3) * 4096;
        const uint32_t Bb = bsb + (it % 3) * 8192;
#pragma unroll
        for (int kb = 0; kb < 2; ++kb) {
            uint32_t af[2][4], bfr[8][2];
#pragma unroll
            for (int mt = 0; mt < 2; ++mt)
                ldsm4(af[mt][0], af[mt][1], af[mt][2], af[mt][3],
                      Ab + rowA[mt] + (((kb * 2 + khalf) ^ swA[mt]) << 4));
#pragma unroll
            for (int g = 0; g < 4; ++g) {
                uint32_t b0, b1, b2, b3;
                ldsm4(b0, b1, b2, b3,
                      Bb + rowB[g] + (((kb * 2 + khalf) ^ swB[g]) << 4));
                bfr[2 * g][0] = b0; bfr[2 * g + 1][0] = b1;
                bfr[2 * g][1] = b2; bfr[2 * g + 1][1] = b3;
            }
#pragma unroll
            for (int mt = 0; mt < 2; ++mt)
#pragma unroll
                for (int nt = 0; nt < 8; ++nt)
                    mma16(acc[mt][nt], af[mt][0], af[mt][1], af[mt][2], af[mt][3],
                          bfr[nt][0], bfr[nt][1]);
        }
    }
}

// -------------------- qkv (128 threads); Q pre-scaled by 0.125*log2e ---------
__global__ void __launch_bounds__(128, 4) qkv_kernel() {
    __shared__ uint32_t As[3 * 1024];
    __shared__ uint32_t Bs[3 * 2048];
    const bf16* W = g_w16 + blockIdx.z * 65536;
    float acc[2][8][4];
    gemm_core2(g_h16, W, D_MODEL, As, Bs, acc);

    const int tid = threadIdx.x, lane = tid & 31, w = tid >> 5;
    const int grp = lane >> 2, qd = lane & 3;
    const int bm = blockIdx.x * 64, bn = blockIdx.y * 128;
    const int wm = (w & 1) * 32, wn = (w >> 1) * 64;

    if (blockIdx.z < 2) {
        bf16* C = (blockIdx.z == 0) ? g_q16 : g_k16;
        const float sc = (blockIdx.z == 0) ? (0.125f * LOG2E) : 1.0f;
#pragma unroll
        for (int mt = 0; mt < 2; ++mt) {
            const int r0 = bm + wm + mt * 16 + grp;
#pragma unroll
            for (int nt = 0; nt < 8; ++nt) {
                const int c = bn + wn + nt * 8 + 2 * qd;
                *(uint32_t*)&C[(size_t)r0 * D_MODEL + c] =
                    pkbf(acc[mt][nt][0] * sc, acc[mt][nt][1] * sc);
                *(uint32_t*)&C[(size_t)(r0 + 8) * D_MODEL + c] =
                    pkbf(acc[mt][nt][2] * sc, acc[mt][nt][3] * sc);
            }
        }
    } else {
#pragma unroll
        for (int mt = 0; mt < 2; ++mt) {
            const int r0 = bm + wm + mt * 16 + grp;
            const int b0 = r0 >> 11, t0 = r0 & 2047;
            const int b1 = (r0 + 8) >> 11, t1 = (r0 + 8) & 2047;
#pragma unroll
            for (int nt = 0; nt < 8; ++nt) {
                const int c = bn + wn + nt * 8 + 2 * qd;
                const int hh = c >> 6, dd = c & 63;
                bf16* p0 = &g_vt16[((size_t)(b0 * 4 + hh) * 64 + dd) * T_ + t0];
                bf16* p1 = &g_vt16[((size_t)(b1 * 4 + hh) * 64 + dd) * T_ + t1];
                p0[0]  = __float2bfloat16(acc[mt][nt][0]);
                p0[T_] = __float2bfloat16(acc[mt][nt][1]);
                p1[0]  = __float2bfloat16(acc[mt][nt][2]);
                p1[T_] = __float2bfloat16(acc[mt][nt][3]);
            }
        }
    }
}

// -------------------- wo / down (128 threads): A16 @ W^T + res -> fp32 --------
__global__ void __launch_bounds__(128, 4) out_gemm_kernel(const bf16* __restrict__ A,
                                                          const bf16* __restrict__ W,
                                                          const float* __restrict__ res,
                                                          float* __restrict__ C, int K) {
    __shared__ uint32_t As[3 * 1024];
    __shared__ uint32_t Bs[3 * 2048];
    float acc[2][8][4];
    gemm_core2(A, W, K, As, Bs, acc);

    const int tid = threadIdx.x, lane = tid & 31, w = tid >> 5;
    const int grp = lane >> 2, qd = lane & 3;
    const int bm = blockIdx.x * 64, bn = blockIdx.y * 128;
    const int wm = (w & 1) * 32, wn = (w >> 1) * 64;
#pragma unroll
    for (int mt = 0; mt < 2; ++mt) {
        const int r0 = bm + wm + mt * 16 + grp;
#pragma unroll
        for (int nt = 0; nt < 8; ++nt) {
            const int c = bn + wn + nt * 8 + 2 * qd;
            float2 v0 = make_float2(acc[mt][nt][0], acc[mt][nt][1]);
            float2 v1 = make_float2(acc[mt][nt][2], acc[mt][nt][3]);
            float2 rr = *(const float2*)&res[(size_t)r0 * D_MODEL + c];
            v0.x += rr.x; v0.y += rr.y;
            rr = *(const float2*)&res[(size_t)(r0 + 8) * D_MODEL + c];
            v1.x += rr.x; v1.y += rr.y;
            *(float2*)&C[(size_t)r0 * D_MODEL + c] = v0;
            *(float2*)&C[(size_t)(r0 + 8) * D_MODEL + c] = v1;
        }
    }
}

// -------------------- fused gate/up/silu v2: 128 thr, warp 32x(32g+32u) -------
// B smem combined: rows 0-63 = Wg[bn..bn+63], rows 64-127 = Wu[bn..bn+63].
__global__ void __launch_bounds__(128, 4) gateup_kernel() {
    __shared__ uint32_t As[3 * 1024];
    __shared__ uint32_t Bs[3 * 2048];
    const int tid = threadIdx.x, lane = tid & 31, w = tid >> 5;
    const int m4 = lane >> 3, r8 = lane & 7;
    const int grp = lane >> 2, qd = lane & 3;
    const int bm = blockIdx.x * 64, bn = blockIdx.y * 64;
    const int wm = (w & 1) * 32, wn2 = (w >> 1) * 32;

    float acc[2][8][4];   // nt 0-3: gate, nt 4-7: up (same columns)
#pragma unroll
    for (int mt = 0; mt < 2; mt++)
#pragma unroll
        for (int nt = 0; nt < 8; nt++)
#pragma unroll
            for (int j = 0; j < 4; j++) acc[mt][nt][j] = 0.f;

    const bf16* Wg = g_w16 + 262144;
    const bf16* Wu = g_w16 + 524288;

    const bf16* gap[2];
    uint32_t aoff[2];
#pragma unroll
    for (int i = 0; i < 2; ++i) {
        const int idx = tid + i * 128, r = idx >> 2, c = idx & 3;
        gap[i] = g_h16 + (size_t)(bm + r) * D_MODEL + c * 8;
        aoff[i] = ((r * 16 + ((c ^ ((r >> 1) & 3)) << 2)) << 2);
    }
    const bf16* gbp[4];
    uint32_t boff[4];
#pragma unroll
    for (int i = 0; i < 4; ++i) {
        const int idx = tid + i * 128, r = idx >> 2, c = idx & 3;
        gbp[i] = (r < 64) ? (Wg + (size_t)(bn + r) * D_MODEL + c * 8)
                          : (Wu + (size_t)(bn + r - 64) * D_MODEL + c * 8);
        boff[i] = ((r * 16 + ((c ^ ((r >> 1) & 3)) << 2)) << 2);
    }
    const uint32_t asb = s2u(As), bsb = s2u(Bs);

    const int khalf = m4 >> 1;
    int rowA[2], swA[2], rowB[4], swB[4];
#pragma unroll
    for (int mt = 0; mt < 2; ++mt) {
        const int R = wm + mt * 16 + (m4 & 1) * 8 + r8;
        rowA[mt] = R * 64;
        swA[mt] = (R >> 1) & 3;
    }
#pragma unroll
    for (int g = 0; g < 4; ++g) {
        // g=0,1: gate rows wn2+{0..15},{16..31}; g=2,3: up rows 64+wn2+{..}
        const int R = ((g >> 1) ? 64 : 0) + wn2 + (2 * (g & 1) + (m4 & 1)) * 8 + r8;
        rowB[g] = R * 64;
        swB[g] = (R >> 1) & 3;
    }

    const int NK = D_MODEL >> 5;  // 8
#pragma unroll
    for (int i = 0; i < 2; ++i) cp16(asb + aoff[i], gap[i]);
#pragma unroll
    for (int i = 0; i < 4; ++i) cp16(bsb + boff[i], gbp[i]);
    CP_COMMIT;
#pragma unroll
    for (int i = 0; i < 2; ++i) cp16(asb + 4096 + aoff[i], gap[i] + 32);
#pragma unroll
    for (int i = 0; i < 4; ++i) cp16(bsb + 8192 + boff[i], gbp[i] + 32);
    CP_COMMIT;

    for (int it = 0; it < NK; ++it) {
        CP_WAIT1;
        __syncthreads();
        if (it + 2 < NK) {
            const int st = (it + 2) % 3;
            const int ko = (it + 2) << 5;
#pragma unroll
            for (int i = 0; i < 2; ++i) cp16(asb + st * 4096 + aoff[i], gap[i] + ko);
#pragma unroll
            for (int i = 0; i < 4; ++i) cp16(bsb + st * 8192 + boff[i], gbp[i] + ko);
        }
        CP_COMMIT;
        const uint32_t Ab = asb + (it % 3) * 4096;
        const uint32_t Bb = bsb + (it % 3) * 8192;
#pragma unroll
        for (int kb = 0; kb < 2; ++kb) {
            uint32_t af[2][4], bfr[8][2];
#pragma unroll
            for (int mt = 0; mt < 2; ++mt)
                ldsm4(af[mt][0], af[mt][1], af[mt][2], af[mt][3],
                      Ab + rowA[mt] + (((kb * 2 + khalf) ^ swA[mt]) << 4));
#pragma unroll
            for (int g = 0; g < 4; ++g) {
                uint32_t b0, b1, b2, b3;
                ldsm4(b0, b1, b2, b3,
                      Bb + rowB[g] + (((kb * 2 + khalf) ^ swB[g]) << 4));
                bfr[2 * g][0] = b0; bfr[2 * g + 1][0] = b1;
                bfr[2 * g][1] = b2; bfr[2 * g + 1][1] = b3;
            }
#pragma unroll
            for (int mt = 0; mt < 2; ++mt)
#pragma unroll
                for (int nt = 0; nt < 8; ++nt)
                    mma16(acc[mt][nt], af[mt][0], af[mt][1], af[mt][2], af[mt][3],
                          bfr[nt][0], bfr[nt][1]);
        }
    }

    // epilogue: silu(gate)*up -> silu16
#pragma unroll
    for (int mt = 0; mt < 2; ++mt) {
        const int r0 = bm + wm + mt * 16 + grp;
#pragma unroll
        for (int nt = 0; nt < 4; ++nt) {
            const int c = bn + wn2 + nt * 8 + 2 * qd;
            float s0[4];
#pragma unroll
            for (int j = 0; j < 4; ++j) {
                const float g = acc[mt][nt][j];
                s0[j] = (g / (1.0f + __expf(-g))) * acc[mt][nt + 4][j];
            }
            *(uint32_t*)&g_silu16[(size_t)r0 * D_FF + c] = pkbf(s0[0], s0[1]);
            *(uint32_t*)&g_silu16[(size_t)(r0 + 8) * D_FF + c] = pkbf(s0[2], s0[3]);
        }
    }
}

// -------------------- flash attention: paired tiles, no-max exp2 -------------
// Grid (16,4,4): block does q-tile x (x+1 ktiles) then 31-x (32-x ktiles) = 33.
// Q pre-scaled by 0.125*log2e in qkv epilogue.
__global__ void __launch_bounds__(128, 3) flash_kernel() {
    __shared__ uint32_t Qs[64 * 32];       // 8KB
    __shared__ uint32_t Ks[2][64 * 32];    // 16KB
    __shared__ uint32_t Vs[2][64 * 32];    // 16KB
    const int xpair = blockIdx.x, h = blockIdx.y, b = blockIdx.z;
    const int tid = threadIdx.x, lane = tid & 31, w = tid >> 5;
    const int m4 = lane >> 3, r8 = lane & 7;
    const int grp = lane >> 2, qd = lane & 3;
    const size_t tok = (size_t)b * T_;
    const int bh = b * 4 + h;
    const bf16* Kg = g_k16 + tok * D_MODEL + h * 64;
    const bf16* Vg = g_vt16 + (size_t)bh * 64 * T_;
    const uint32_t ksb = s2u(Ks), vsb = s2u(Vs);
    const uint32_t qsb = s2u(Qs);
    const int khalf = m4 >> 1;

    // hoisted LDSM column offsets (loop-invariant)
    uint32_t co4[4];
#pragma unroll
    for (int kb = 0; kb < 4; ++kb) co4[kb] = (uint32_t)(((kb * 2 + khalf) ^ r8) << 4);

    const uint32_t aQ = qsb + (uint32_t)((w * 16 + (m4 & 1) * 8 + r8) * 128);
    int rowKV[4];
#pragma unroll
    for (int g = 0; g < 4; ++g) rowKV[g] = ((2 * g + (m4 & 1)) * 8 + r8) * 128;

    // hoisted cp.async per-thread maps: rows pr, pr+16, pr+32, pr+48 (r&7 inv.)
    const int pr = tid >> 3, pc = tid & 7;
    const uint32_t so0 = (uint32_t)((pr * 32 + ((pc ^ (pr & 7)) << 2)) << 2);
    const bf16* kbase = Kg + (size_t)pr * D_MODEL + pc * 8;
    const bf16* vbase = Vg + (size_t)pr * T_ + pc * 8;

    for (int rep = 0; rep < 2; ++rep) {
        const int qbi = rep ? (31 - xpair) : xpair;
        const int q0 = qbi * 64;
        const int qw = q0 + w * 16;
        const bf16* Qg = g_q16 + (tok + q0) * D_MODEL + h * 64;

        __syncthreads();  // all warps done with prior rep's buffers + Qs

        // issue kv tile 0 into buffer 0
#pragma unroll
        for (int i = 0; i < 4; ++i) {
            cp16(ksb + so0 + i * 2048, kbase + (size_t)i * 16 * D_MODEL);
            cp16(vsb + so0 + i * 2048, vbase + (size_t)i * 16 * T_);
        }
        CP_COMMIT;

        // load Q tile
#pragma unroll
        for (int i = 0; i < 4; ++i) {
            const int idx = tid + i * 128;
            const int r = idx >> 3, c = idx & 7;
            const uint4 v = *(const uint4*)(Qg + (size_t)r * D_MODEL + c * 8);
            *(uint4*)&Qs[r * 32 + ((c ^ (r & 7)) << 2)] = v;
        }

        float o[8][4];
        float li0 = 0.f, li1 = 0.f;
#pragma unroll
        for (int nt = 0; nt < 8; nt++)
#pragma unroll
            for (int j = 0; j < 4; j++) o[nt][j] = 0.f;

        const int ntiles = qbi + 1;
        for (int kt = 0; kt < ntiles; ++kt) {
            const int k0 = kt * 64;
            CP_WAIT0;
            __syncthreads();
            if (kt + 1 < ntiles) {
                const uint32_t stoff = ((kt + 1) & 1) * 8192;
                const int kn = (kt + 1) * 64;
                const bf16* kp = kbase + (size_t)kn * D_MODEL;
                const bf16* vp = vbase + kn;
#pragma unroll
                for (int i = 0; i < 4; ++i) {
                    cp16(ksb + stoff + so0 + i * 2048, kp + (size_t)i * 16 * D_MODEL);
                    cp16(vsb + stoff + so0 + i * 2048, vp + (size_t)i * 16 * T_);
                }
                CP_COMMIT;
            }
            if (k0 > qw + 15) continue;
            const uint32_t Kb = ksb + (kt & 1) * 8192;
            const uint32_t Vb = vsb + (kt & 1) * 8192;

            // S = Q K^T (warp: 16 x 64)
            float s[8][4];
#pragma unroll
            for (int nt = 0; nt < 8; nt++)
#pragma unroll
                for (int j = 0; j < 4; j++) s[nt][j] = 0.f;
#pragma unroll
            for (int kb = 0; kb < 4; ++kb) {
                uint32_t a0, a1, a2, a3;
                ldsm4(a0, a1, a2, a3, aQ + co4[kb]);
                uint32_t kf[8][2];
#pragma unroll
                for (int g = 0; g < 4; ++g) {
                    uint32_t b0, b1, b2, b3;
                    ldsm4(b0, b1, b2, b3, Kb + rowKV[g] + co4[kb]);
                    kf[2 * g][0] = b0; kf[2 * g + 1][0] = b1;
                    kf[2 * g][1] = b2; kf[2 * g + 1][1] = b3;
                }
#pragma unroll
                for (int nt = 0; nt < 8; ++nt)
                    mma16(s[nt], a0, a1, a2, a3, kf[nt][0], kf[nt][1]);
            }

            // causal mask + exp2 (Q pre-scaled; no running max needed)
            const int r0 = qw + grp, r1 = r0 + 8;
            const bool diag = (k0 + 63 > qw);
            float sum0 = 0.f, sum1 = 0.f;
#pragma unroll
            for (int nt = 0; nt < 8; nt++) {
                float v0 = s[nt][0], v1 = s[nt][1], v2 = s[nt][2], v3 = s[nt][3];
                if (diag) {
                    const int c0 = k0 + nt * 8 + 2 * qd;
                    if (c0 > r0) v0 = -1e30f;
                    if (c0 + 1 > r0) v1 = -1e30f;
                    if (c0 > r1) v2 = -1e30f;
                    if (c0 + 1 > r1) v3 = -1e30f;
                }
                s[nt][0] = ex2(v0);
                s[nt][1] = ex2(v1);
                s[nt][2] = ex2(v2);
                s[nt][3] = ex2(v3);
                sum0 += s[nt][0] + s[nt][1];
                sum1 += s[nt][2] + s[nt][3];
            }
            li0 += sum0;
            li1 += sum1;

            // pack P into A-fragments (registers only)
            uint32_t pa[4][4];
#pragma unroll
            for (int ks = 0; ks < 4; ++ks) {
                pa[ks][0] = pkbf(s[2 * ks][0], s[2 * ks][1]);
                pa[ks][1] = pkbf(s[2 * ks][2], s[2 * ks][3]);
                pa[ks][2] = pkbf(s[2 * ks + 1][0], s[2 * ks + 1][1]);
                pa[ks][3] = pkbf(s[2 * ks + 1][2], s[2 * ks + 1][3]);
            }

            // O += P @ V
#pragma unroll
            for (int ks = 0; ks < 4; ++ks) {
                uint32_t vf[8][2];
#pragma unroll
                for (int g = 0; g < 4; ++g) {
                    uint32_t b0, b1, b2, b3;
                    ldsm4(b0, b1, b2, b3, Vb + rowKV[g] + co4[ks]);
                    vf[2 * g][0] = b0; vf[2 * g + 1][0] = b1;
                    vf[2 * g][1] = b2; vf[2 * g + 1][1] = b3;
                }
#pragma unroll
                for (int nt = 0; nt < 8; ++nt)
                    mma16(o[nt], pa[ks][0], pa[ks][1], pa[ks][2], pa[ks][3],
                          vf[nt][0], vf[nt][1]);
            }
        }

        // row-sum reduction across 4-lane groups
        li0 += __shfl_xor_sync(0xffffffffu, li0, 1);
        li0 += __shfl_xor_sync(0xffffffffu, li0, 2);
        li1 += __shfl_xor_sync(0xffffffffu, li1, 1);
        li1 += __shfl_xor_sync(0xffffffffu, li1, 2);

        // epilogue -> attn16 [token][256]
        const float inv0 = 1.0f / li0, inv1 = 1.0f / li1;
        const int r0 = qw + grp;
#pragma unroll
        for (int nt = 0; nt < 8; ++nt) {
            const int c = h * 64 + nt * 8 + 2 * qd;
            *(uint32_t*)&g_attn16[(tok + r0) * D_MODEL + c] = pkbf(o[nt][0] * inv0, o[nt][1] * inv0);
            *(uint32_t*)&g_attn16[(tok + r0 + 8) * D_MODEL + c] = pkbf(o[nt][2] * inv1, o[nt][3] * inv1);
        }
    }
}

// -------------------- launch --------------------
extern "C" void kernel_launch(void* const* d_in, const int* in_sizes, int n_in,
                              void* d_out, int out_size) {
    const float* x          = (const float*)d_in[0];
    const float* rms_attn_w = (const float*)d_in[2];
    const float* wq         = (const float*)d_in[3];
    const float* wk         = (const float*)d_in[4];
    const float* wv         = (const float*)d_in[5];
    const float* wo         = (const float*)d_in[6];
    const float* rms_ffn_w  = (const float*)d_in[7];
    const float* wg         = (const float*)d_in[8];
    const float* wu         = (const float*)d_in[9];
    const float* wd         = (const float*)d_in[10];
    float* out = (float*)d_out;

    bf16 *w16, *attn16, *silu16;
    float* x1;
    cudaGetSymbolAddress((void**)&w16, g_w16);
    cudaGetSymbolAddress((void**)&attn16, g_attn16);
    cudaGetSymbolAddress((void**)&silu16, g_silu16);
    cudaGetSymbolAddress((void**)&x1, g_x1);

    // 1. convert weights to bf16
    cvtw_kernel<<<dim3(256, 7), 256>>>(wq, wk, wv, wo, wg, wu, wd);
    // 2. h16 = rmsnorm(x)
    rmsnorm_kernel<<<BT, 256>>>(x, rms_attn_w);
    // 3. q(scaled),k,vt
    qkv_kernel<<<dim3(BT / 64, 2, 3), 128>>>();
    // 4. attention (balanced causal pairs)
    flash_kernel<<<dim3(16, 4, B_), 128>>>();
    // 5. x1 = x + attn @ wo^T
    out_gemm_kernel<<<dim3(BT / 64, 2), 128>>>(attn16, w16 + 196608, x, x1, D_MODEL);
    // 6. h16 = rmsnorm(x1)
    rmsnorm_kernel<<<BT, 256>>>(x1, rms_ffn_w);
    // 7. silu16 = silu(h16@wg^T) * (h16@wu^T)
    gateup_kernel<<<dim3(BT / 64, D_FF / 64), 128>>>();
    // 8. out = x1 + silu16 @ wd^T
    out_gemm_kernel<<<dim3(BT / 64, 2), 128>>>(silu16, w16 + 786432, x1, out, D_FF);
}

// round 17
// speedup vs baseline: 1.0813x; 1.0813x over previous
#include <cuda_runtime.h>
#include <cuda_bf16.h>
#include <stdint.h>
#include <math.h>

#define D_MODEL 256
#define D_FF    1024
#define T_      2048
#define B_      4
#define BT      8192
#define RMS_EPS 1e-5f
#define LOG2E   1.4426950408889634f

typedef __nv_bfloat16 bf16;

// -------------------- scratch (no allocs allowed) --------------------
__device__ bf16  g_w16[1048576];
__device__ bf16  g_h16[BT * D_MODEL];
__device__ bf16  g_q16[BT * D_MODEL];    // pre-scaled by 0.125*log2e
__device__ bf16  g_k16[BT * D_MODEL];
__device__ bf16  g_vt16[BT * D_MODEL];   // v transposed: [(b*4+h)*64+d][t]
__device__ bf16  g_attn16[BT * D_MODEL];
__device__ bf16  g_silu16[BT * D_FF];
__device__ float g_x1[BT * D_MODEL];

// -------------------- helpers --------------------
__device__ __forceinline__ uint32_t pkbf(float lo, float hi) {
    uint32_t r;
    asm("cvt.rn.bf16x2.f32 %0,%1,%2;" : "=r"(r) : "f"(hi), "f"(lo));
    return r;
}
__device__ __forceinline__ float ex2(float x) {
    float y;
    asm("ex2.approx.f32 %0,%1;" : "=f"(y) : "f"(x));
    return y;
}
__device__ __forceinline__ void mma16(float* d, uint32_t a0, uint32_t a1, uint32_t a2,
                                      uint32_t a3, uint32_t b0, uint32_t b1) {
    asm volatile(
        "mma.sync.aligned.m16n8k16.row.col.f32.bf16.bf16.f32 "
        "{%0,%1,%2,%3},{%4,%5,%6,%7},{%8,%9},{%0,%1,%2,%3};"
        : "+f"(d[0]), "+f"(d[1]), "+f"(d[2]), "+f"(d[3])
        : "r"(a0), "r"(a1), "r"(a2), "r"(a3), "r"(b0), "r"(b1));
}
__device__ __forceinline__ void ldsm4(uint32_t& r0, uint32_t& r1, uint32_t& r2,
                                      uint32_t& r3, uint32_t addr) {
    asm volatile("ldmatrix.sync.aligned.m8n8.x4.shared.b16 {%0,%1,%2,%3},[%4];"
                 : "=r"(r0), "=r"(r1), "=r"(r2), "=r"(r3) : "r"(addr));
}
__device__ __forceinline__ uint32_t s2u(const void* p) {
    return (uint32_t)__cvta_generic_to_shared(p);
}
__device__ __forceinline__ void cp16(uint32_t s, const void* g) {
    asm volatile("cp.async.cg.shared.global [%0],[%1],16;" :: "r"(s), "l"(g) : "memory");
}
#define CP_COMMIT asm volatile("cp.async.commit_group;" ::: "memory")
#define CP_WAIT0  asm volatile("cp.async.wait_group 0;" ::: "memory")
#define CP_WAIT1  asm volatile("cp.async.wait_group 1;" ::: "memory")

// -------------------- weight fp32 -> bf16 --------------------
__global__ void cvtw_kernel(const float* __restrict__ wq, const float* __restrict__ wk,
                            const float* __restrict__ wv, const float* __restrict__ wo,
                            const float* __restrict__ wg, const float* __restrict__ wu,
                            const float* __restrict__ wd) {
    const float* src; int n, off;
    switch (blockIdx.y) {
        case 0: src = wq; n = 65536;  off = 0;      break;
        case 1: src = wk; n = 65536;  off = 65536;  break;
        case 2: src = wv; n = 65536;  off = 131072; break;
        case 3: src = wo; n = 65536;  off = 196608; break;
        case 4: src = wg; n = 262144; off = 262144; break;
        case 5: src = wu; n = 262144; off = 524288; break;
        default: src = wd; n = 262144; off = 786432; break;
    }
    const int i = (blockIdx.x * 256 + threadIdx.x) * 4;
    if (i < n) {
        const float4 v = *(const float4*)(src + i);
        uint2 u = make_uint2(pkbf(v.x, v.y), pkbf(v.z, v.w));
        *(uint2*)&g_w16[off + i] = u;
    }
}

// -------------------- rmsnorm -> bf16 into g_h16 --------------------
__global__ void rmsnorm_kernel(const float* __restrict__ x, const float* __restrict__ w) {
    const int row = blockIdx.x;
    const int tid = threadIdx.x;
    const float v = x[(size_t)row * D_MODEL + tid];
    float ss = v * v;
#pragma unroll
    for (int m = 16; m; m >>= 1) ss += __shfl_xor_sync(0xffffffffu, ss, m);
    __shared__ float ws[8];
    __shared__ float s_tot;
    if ((tid & 31) == 0) ws[tid >> 5] = ss;
    __syncthreads();
    if (tid < 8) {
        float t = ws[tid];
        t += __shfl_xor_sync(0xffu, t, 4);
        t += __shfl_xor_sync(0xffu, t, 2);
        t += __shfl_xor_sync(0xffu, t, 1);
        if (tid == 0) s_tot = t;
    }
    __syncthreads();
    const float r = rsqrtf(s_tot * (1.0f / D_MODEL) + RMS_EPS);
    g_h16[(size_t)row * D_MODEL + tid] = __float2bfloat16(v * r * w[tid]);
}

// -------------------- bf16 GEMM core v2: BM=64 BN=128 BK=32, 128 thr ---------
__device__ __forceinline__ void gemm_core2(const bf16* __restrict__ A,
                                           const bf16* __restrict__ W,
                                           int K, uint32_t* As, uint32_t* Bs,
                                           float (&acc)[2][8][4]) {
    const int tid = threadIdx.x, lane = tid & 31, w = tid >> 5;
    const int m4 = lane >> 3, r8 = lane & 7;
    const int bm = blockIdx.x * 64, bn = blockIdx.y * 128;
    const int wm = (w & 1) * 32, wn = (w >> 1) * 64;

#pragma unroll
    for (int mt = 0; mt < 2; mt++)
#pragma unroll
        for (int nt = 0; nt < 8; nt++)
#pragma unroll
            for (int j = 0; j < 4; j++) acc[mt][nt][j] = 0.f;

    const bf16* gap[2];
    uint32_t aoff[2];
#pragma unroll
    for (int i = 0; i < 2; ++i) {
        const int idx = tid + i * 128, r = idx >> 2, c = idx & 3;
        gap[i] = A + (size_t)(bm + r) * K + c * 8;
        aoff[i] = ((r * 16 + ((c ^ ((r >> 1) & 3)) << 2)) << 2);
    }
    const bf16* gbp[4];
    uint32_t boff[4];
#pragma unroll
    for (int i = 0; i < 4; ++i) {
        const int idx = tid + i * 128, r = idx >> 2, c = idx & 3;
        gbp[i] = W + (size_t)(bn + r) * K + c * 8;
        boff[i] = ((r * 16 + ((c ^ ((r >> 1) & 3)) << 2)) << 2);
    }
    const uint32_t asb = s2u(As), bsb = s2u(Bs);

    const int khalf = m4 >> 1;
    int rowA[2], swA[2], rowB[4], swB[4];
#pragma unroll
    for (int mt = 0; mt < 2; ++mt) {
        const int R = wm + mt * 16 + (m4 & 1) * 8 + r8;
        rowA[mt] = R * 64;
        swA[mt] = (R >> 1) & 3;
    }
#pragma unroll
    for (int g = 0; g < 4; ++g) {
        const int R = wn + (2 * g + (m4 & 1)) * 8 + r8;
        rowB[g] = R * 64;
        swB[g] = (R >> 1) & 3;
    }

    const int NK = K >> 5;
#pragma unroll
    for (int i = 0; i < 2; ++i) cp16(asb + aoff[i], gap[i]);
#pragma unroll
    for (int i = 0; i < 4; ++i) cp16(bsb + boff[i], gbp[i]);
    CP_COMMIT;
    if (NK > 1) {
#pragma unroll
        for (int i = 0; i < 2; ++i) cp16(asb + 4096 + aoff[i], gap[i] + 32);
#pragma unroll
        for (int i = 0; i < 4; ++i) cp16(bsb + 8192 + boff[i], gbp[i] + 32);
    }
    CP_COMMIT;

    for (int it = 0; it < NK; ++it) {
        CP_WAIT1;
        __syncthreads();
        if (it + 2 < NK) {
            const int st = (it + 2) % 3;
            const int ko = (it + 2) << 5;
#pragma unroll
            for (int i = 0; i < 2; ++i) cp16(asb + st * 4096 + aoff[i], gap[i] + ko);
#pragma unroll
            for (int i = 0; i < 4; ++i) cp16(bsb + st * 8192 + boff[i], gbp[i] + ko);
        }
        CP_COMMIT;
        const uint32_t Ab = asb + (it % 3) * 4096;
        const uint32_t Bb = bsb + (it % 3) * 8192;
#pragma unroll
        for (int kb = 0; kb < 2; ++kb) {
            uint32_t af[2][4], bfr[8][2];
#pragma unroll
            for (int mt = 0; mt < 2; ++mt)
                ldsm4(af[mt][0], af[mt][1], af[mt][2], af[mt][3],
                      Ab + rowA[mt] + (((kb * 2 + khalf) ^ swA[mt]) << 4));
#pragma unroll
            for (int g = 0; g < 4; ++g) {
                uint32_t b0, b1, b2, b3;
                ldsm4(b0, b1, b2, b3,
                      Bb + rowB[g] + (((kb * 2 + khalf) ^ swB[g]) << 4));
                bfr[2 * g][0] = b0; bfr[2 * g + 1][0] = b1;
                bfr[2 * g][1] = b2; bfr[2 * g + 1][1] = b3;
            }
#pragma unroll
            for (int mt = 0; mt < 2; ++mt)
#pragma unroll
                for (int nt = 0; nt < 8; ++nt)
                    mma16(acc[mt][nt], af[mt][0], af[mt][1], af[mt][2], af[mt][3],
                          bfr[nt][0], bfr[nt][1]);
        }
    }
}

// -------------------- qkv (128 threads); Q pre-scaled by 0.125*log2e ---------
__global__ void __launch_bounds__(128, 4) qkv_kernel() {
    __shared__ uint32_t As[3 * 1024];
    __shared__ uint32_t Bs[3 * 2048];
    const bf16* W = g_w16 + blockIdx.z * 65536;
    float acc[2][8][4];
    gemm_core2(g_h16, W, D_MODEL, As, Bs, acc);

    const int tid = threadIdx.x, lane = tid & 31, w = tid >> 5;
    const int grp = lane >> 2, qd = lane & 3;
    const int bm = blockIdx.x * 64, bn = blockIdx.y * 128;
    const int wm = (w & 1) * 32, wn = (w >> 1) * 64;

    if (blockIdx.z < 2) {
        bf16* C = (blockIdx.z == 0) ? g_q16 : g_k16;
        const float sc = (blockIdx.z == 0) ? (0.125f * LOG2E) : 1.0f;
#pragma unroll
        for (int mt = 0; mt < 2; ++mt) {
            const int r0 = bm + wm + mt * 16 + grp;
#pragma unroll
            for (int nt = 0; nt < 8; ++nt) {
                const int c = bn + wn + nt * 8 + 2 * qd;
                *(uint32_t*)&C[(size_t)r0 * D_MODEL + c] =
                    pkbf(acc[mt][nt][0] * sc, acc[mt][nt][1] * sc);
                *(uint32_t*)&C[(size_t)(r0 + 8) * D_MODEL + c] =
                    pkbf(acc[mt][nt][2] * sc, acc[mt][nt][3] * sc);
            }
        }
    } else {
#pragma unroll
        for (int mt = 0; mt < 2; ++mt) {
            const int r0 = bm + wm + mt * 16 + grp;
            const int b0 = r0 >> 11, t0 = r0 & 2047;
            const int b1 = (r0 + 8) >> 11, t1 = (r0 + 8) & 2047;
#pragma unroll
            for (int nt = 0; nt < 8; ++nt) {
                const int c = bn + wn + nt * 8 + 2 * qd;
                const int hh = c >> 6, dd = c & 63;
                bf16* p0 = &g_vt16[((size_t)(b0 * 4 + hh) * 64 + dd) * T_ + t0];
                bf16* p1 = &g_vt16[((size_t)(b1 * 4 + hh) * 64 + dd) * T_ + t1];
                p0[0]  = __float2bfloat16(acc[mt][nt][0]);
                p0[T_] = __float2bfloat16(acc[mt][nt][1]);
                p1[0]  = __float2bfloat16(acc[mt][nt][2]);
                p1[T_] = __float2bfloat16(acc[mt][nt][3]);
            }
        }
    }
}

// -------------------- down proj (128 threads): A16 @ W^T + res -> fp32 --------
__global__ void __launch_bounds__(128, 4) out_gemm_kernel(const bf16* __restrict__ A,
                                                          const bf16* __restrict__ W,
                                                          const float* __restrict__ res,
                                                          float* __restrict__ C, int K) {
    __shared__ uint32_t As[3 * 1024];
    __shared__ uint32_t Bs[3 * 2048];
    float acc[2][8][4];
    gemm_core2(A, W, K, As, Bs, acc);

    const int tid = threadIdx.x, lane = tid & 31, w = tid >> 5;
    const int grp = lane >> 2, qd = lane & 3;
    const int bm = blockIdx.x * 64, bn = blockIdx.y * 128;
    const int wm = (w & 1) * 32, wn = (w >> 1) * 64;
#pragma unroll
    for (int mt = 0; mt < 2; ++mt) {
        const int r0 = bm + wm + mt * 16 + grp;
#pragma unroll
        for (int nt = 0; nt < 8; ++nt) {
            const int c = bn + wn + nt * 8 + 2 * qd;
            float2 v0 = make_float2(acc[mt][nt][0], acc[mt][nt][1]);
            float2 v1 = make_float2(acc[mt][nt][2], acc[mt][nt][3]);
            float2 rr = *(const float2*)&res[(size_t)r0 * D_MODEL + c];
            v0.x += rr.x; v0.y += rr.y;
            rr = *(const float2*)&res[(size_t)(r0 + 8) * D_MODEL + c];
            v1.x += rr.x; v1.y += rr.y;
            *(float2*)&C[(size_t)r0 * D_MODEL + c] = v0;
            *(float2*)&C[(size_t)(r0 + 8) * D_MODEL + c] = v1;
        }
    }
}

// -------------------- fused wo GEMM + residual + rmsnorm: BM=64 BN=256 --------
// 256 threads, 8 warps (2M x 4N). Writes x1 (fp32) and h16 = rmsnorm(x1)*w.
__global__ void __launch_bounds__(256, 1) wo_norm_kernel(const bf16* __restrict__ A,
                                                         const bf16* __restrict__ W,
                                                         const float* __restrict__ res,
                                                         const float* __restrict__ wnorm,
                                                         float* __restrict__ x1out) {
    extern __shared__ uint32_t dsm[];
    uint32_t* As = dsm;                 // 3 stages x 1024 words (64 rows x 16w)
    uint32_t* Bs = dsm + 3 * 1024;      // 3 stages x 4096 words (256 rows x 16w)
    float* rsum = (float*)(dsm + 3 * 1024 + 3 * 4096);   // [64]
    float* wsm  = rsum + 64;                             // [256]

    const int tid = threadIdx.x, lane = tid & 31, w = tid >> 5;
    const int m4 = lane >> 3, r8 = lane & 7;
    const int grp = lane >> 2, qd = lane & 3;
    const int bm = blockIdx.x * 64;
    const int wm = (w & 1) * 32, wn = (w >> 1) * 64;

    if (tid < 64) rsum[tid] = 0.f;
    wsm[tid] = wnorm[tid];

    float acc[2][8][4];
#pragma unroll
    for (int mt = 0; mt < 2; mt++)
#pragma unroll
        for (int nt = 0; nt < 8; nt++)
#pragma unroll
            for (int j = 0; j < 4; j++) acc[mt][nt][j] = 0.f;

    // cp maps: A 1/thread (64x4 chunks), B 4/thread (256x4 chunks)
    const int arr = tid >> 2, arc = tid & 3;
    const bf16* ga = A + (size_t)(bm + arr) * D_MODEL + arc * 8;
    const uint32_t aoff = ((arr * 16 + ((arc ^ ((arr >> 1) & 3)) << 2)) << 2);
    const bf16* gbp[4];
    uint32_t boff[4];
#pragma unroll
    for (int i = 0; i < 4; ++i) {
        const int idx = tid + i * 256, r = idx >> 2, c = idx & 3;
        gbp[i] = W + (size_t)r * D_MODEL + c * 8;
        boff[i] = ((r * 16 + ((c ^ ((r >> 1) & 3)) << 2)) << 2);
    }
    const uint32_t asb = s2u(As), bsb = s2u(Bs);

    const int khalf = m4 >> 1;
    int rowA[2], swA[2], rowB[4], swB[4];
#pragma unroll
    for (int mt = 0; mt < 2; ++mt) {
        const int R = wm + mt * 16 + (m4 & 1) * 8 + r8;
        rowA[mt] = R * 64;
        swA[mt] = (R >> 1) & 3;
    }
#pragma unroll
    for (int g = 0; g < 4; ++g) {
        const int R = wn + (2 * g + (m4 & 1)) * 8 + r8;
        rowB[g] = R * 64;
        swB[g] = (R >> 1) & 3;
    }

    const int NK = D_MODEL >> 5;  // 8
    cp16(asb + aoff, ga);
#pragma unroll
    for (int i = 0; i < 4; ++i) cp16(bsb + boff[i], gbp[i]);
    CP_COMMIT;
    cp16(asb + 4096 + aoff, ga + 32);
#pragma unroll
    for (int i = 0; i < 4; ++i) cp16(bsb + 16384 + boff[i], gbp[i] + 32);
    CP_COMMIT;

    for (int it = 0; it < NK; ++it) {
        CP_WAIT1;
        __syncthreads();
        if (it + 2 < NK) {
            const int st = (it + 2) % 3;
            const int ko = (it + 2) << 5;
            cp16(asb + st * 4096 + aoff, ga + ko);
#pragma unroll
            for (int i = 0; i < 4; ++i) cp16(bsb + st * 16384 + boff[i], gbp[i] + ko);
        }
        CP_COMMIT;
        const uint32_t Ab = asb + (it % 3) * 4096;
        const uint32_t Bb = bsb + (it % 3) * 16384;
#pragma unroll
        for (int kb = 0; kb < 2; ++kb) {
            uint32_t af[2][4], bfr[8][2];
#pragma unroll
            for (int mt = 0; mt < 2; ++mt)
                ldsm4(af[mt][0], af[mt][1], af[mt][2], af[mt][3],
                      Ab + rowA[mt] + (((kb * 2 + khalf) ^ swA[mt]) << 4));
#pragma unroll
            for (int g = 0; g < 4; ++g) {
                uint32_t b0, b1, b2, b3;
                ldsm4(b0, b1, b2, b3,
                      Bb + rowB[g] + (((kb * 2 + khalf) ^ swB[g]) << 4));
                bfr[2 * g][0] = b0; bfr[2 * g + 1][0] = b1;
                bfr[2 * g][1] = b2; bfr[2 * g + 1][1] = b3;
            }
#pragma unroll
            for (int mt = 0; mt < 2; ++mt)
#pragma unroll
                for (int nt = 0; nt < 8; ++nt)
                    mma16(acc[mt][nt], af[mt][0], af[mt][1], af[mt][2], af[mt][3],
                          bfr[nt][0], bfr[nt][1]);
        }
    }

    // epilogue: x1 = acc + res; row sum-of-squares; h16 = x1 * rsqrt * w
    float ssq[2][2] = {{0.f, 0.f}, {0.f, 0.f}};
#pragma unroll
    for (int mt = 0; mt < 2; ++mt) {
        const int r0 = bm + wm + mt * 16 + grp;
#pragma unroll
        for (int nt = 0; nt < 8; ++nt) {
            const int c = wn + nt * 8 + 2 * qd;
            float2 rr = *(const float2*)&res[(size_t)r0 * D_MODEL + c];
            acc[mt][nt][0] += rr.x; acc[mt][nt][1] += rr.y;
            rr = *(const float2*)&res[(size_t)(r0 + 8) * D_MODEL + c];
            acc[mt][nt][2] += rr.x; acc[mt][nt][3] += rr.y;
            *(float2*)&x1out[(size_t)r0 * D_MODEL + c] =
                make_float2(acc[mt][nt][0], acc[mt][nt][1]);
            *(float2*)&x1out[(size_t)(r0 + 8) * D_MODEL + c] =
                make_float2(acc[mt][nt][2], acc[mt][nt][3]);
            ssq[mt][0] += acc[mt][nt][0] * acc[mt][nt][0] + acc[mt][nt][1] * acc[mt][nt][1];
            ssq[mt][1] += acc[mt][nt][2] * acc[mt][nt][2] + acc[mt][nt][3] * acc[mt][nt][3];
        }
    }
#pragma unroll
    for (int mt = 0; mt < 2; ++mt) {
        ssq[mt][0] += __shfl_xor_sync(0xffffffffu, ssq[mt][0], 1);
        ssq[mt][0] += __shfl_xor_sync(0xffffffffu, ssq[mt][0], 2);
        ssq[mt][1] += __shfl_xor_sync(0xffffffffu, ssq[mt][1], 1);
        ssq[mt][1] += __shfl_xor_sync(0xffffffffu, ssq[mt][1], 2);
        if (qd == 0) {
            atomicAdd(&rsum[wm + mt * 16 + grp], ssq[mt][0]);
            atomicAdd(&rsum[wm + mt * 16 + grp + 8], ssq[mt][1]);
        }
    }
    __syncthreads();
#pragma unroll
    for (int mt = 0; mt < 2; ++mt) {
        const int lr = wm + mt * 16 + grp;
        const int r0 = bm + lr;
        const float s0 = rsqrtf(rsum[lr] * (1.0f / D_MODEL) + RMS_EPS);
        const float s1 = rsqrtf(rsum[lr + 8] * (1.0f / D_MODEL) + RMS_EPS);
#pragma unroll
        for (int nt = 0; nt < 8; ++nt) {
            const int c = wn + nt * 8 + 2 * qd;
            const float w0 = wsm[c], w1 = wsm[c + 1];
            *(uint32_t*)&g_h16[(size_t)r0 * D_MODEL + c] =
                pkbf(acc[mt][nt][0] * s0 * w0, acc[mt][nt][1] * s0 * w1);
            *(uint32_t*)&g_h16[(size_t)(r0 + 8) * D_MODEL + c] =
                pkbf(acc[mt][nt][2] * s1 * w0, acc[mt][nt][3] * s1 * w1);
        }
    }
}

// -------------------- fused gate/up/silu v2: 128 thr, warp 32x(32g+32u) -------
__global__ void __launch_bounds__(128, 4) gateup_kernel() {
    __shared__ uint32_t As[3 * 1024];
    __shared__ uint32_t Bs[3 * 2048];
    const int tid = threadIdx.x, lane = tid & 31, w = tid >> 5;
    const int m4 = lane >> 3, r8 = lane & 7;
    const int grp = lane >> 2, qd = lane & 3;
    const int bm = blockIdx.x * 64, bn = blockIdx.y * 64;
    const int wm = (w & 1) * 32, wn2 = (w >> 1) * 32;

    float acc[2][8][4];   // nt 0-3: gate, nt 4-7: up (same columns)
#pragma unroll
    for (int mt = 0; mt < 2; mt++)
#pragma unroll
        for (int nt = 0; nt < 8; nt++)
#pragma unroll
            for (int j = 0; j < 4; j++) acc[mt][nt][j] = 0.f;

    const bf16* Wg = g_w16 + 262144;
    const bf16* Wu = g_w16 + 524288;

    const bf16* gap[2];
    uint32_t aoff[2];
#pragma unroll
    for (int i = 0; i < 2; ++i) {
        const int idx = tid + i * 128, r = idx >> 2, c = idx & 3;
        gap[i] = g_h16 + (size_t)(bm + r) * D_MODEL + c * 8;
        aoff[i] = ((r * 16 + ((c ^ ((r >> 1) & 3)) << 2)) << 2);
    }
    const bf16* gbp[4];
    uint32_t boff[4];
#pragma unroll
    for (int i = 0; i < 4; ++i) {
        const int idx = tid + i * 128, r = idx >> 2, c = idx & 3;
        gbp[i] = (r < 64) ? (Wg + (size_t)(bn + r) * D_MODEL + c * 8)
                          : (Wu + (size_t)(bn + r - 64) * D_MODEL + c * 8);
        boff[i] = ((r * 16 + ((c ^ ((r >> 1) & 3)) << 2)) << 2);
    }
    const uint32_t asb = s2u(As), bsb = s2u(Bs);

    const int khalf = m4 >> 1;
    int rowA[2], swA[2], rowB[4], swB[4];
#pragma unroll
    for (int mt = 0; mt < 2; ++mt) {
        const int R = wm + mt * 16 + (m4 & 1) * 8 + r8;
        rowA[mt] = R * 64;
        swA[mt] = (R >> 1) & 3;
    }
#pragma unroll
    for (int g = 0; g < 4; ++g) {
        const int R = ((g >> 1) ? 64 : 0) + wn2 + (2 * (g & 1) + (m4 & 1)) * 8 + r8;
        rowB[g] = R * 64;
        swB[g] = (R >> 1) & 3;
    }

    const int NK = D_MODEL >> 5;  // 8
#pragma unroll
    for (int i = 0; i < 2; ++i) cp16(asb + aoff[i], gap[i]);
#pragma unroll
    for (int i = 0; i < 4; ++i) cp16(bsb + boff[i], gbp[i]);
    CP_COMMIT;
#pragma unroll
    for (int i = 0; i < 2; ++i) cp16(asb + 4096 + aoff[i], gap[i] + 32);
#pragma unroll
    for (int i = 0; i < 4; ++i) cp16(bsb + 8192 + boff[i], gbp[i] + 32);
    CP_COMMIT;

    for (int it = 0; it < NK; ++it) {
        CP_WAIT1;
        __syncthreads();
        if (it + 2 < NK) {
            const int st = (it + 2) % 3;
            const int ko = (it + 2) << 5;
#pragma unroll
            for (int i = 0; i < 2; ++i) cp16(asb + st * 4096 + aoff[i], gap[i] + ko);
#pragma unroll
            for (int i = 0; i < 4; ++i) cp16(bsb + st * 8192 + boff[i], gbp[i] + ko);
        }
        CP_COMMIT;
        const uint32_t Ab = asb + (it % 3) * 4096;
        const uint32_t Bb = bsb + (it % 3) * 8192;
#pragma unroll
        for (int kb = 0; kb < 2; ++kb) {
            uint32_t af[2][4], bfr[8][2];
#pragma unroll
            for (int mt = 0; mt < 2; ++mt)
                ldsm4(af[mt][0], af[mt][1], af[mt][2], af[mt][3],
                      Ab + rowA[mt] + (((kb * 2 + khalf) ^ swA[mt]) << 4));
#pragma unroll
            for (int g = 0; g < 4; ++g) {
                uint32_t b0, b1, b2, b3;
                ldsm4(b0, b1, b2, b3,
                      Bb + rowB[g] + (((kb * 2 + khalf) ^ swB[g]) << 4));
                bfr[2 * g][0] = b0; bfr[2 * g + 1][0] = b1;
                bfr[2 * g][1] = b2; bfr[2 * g + 1][1] = b3;
            }
#pragma unroll
            for (int mt = 0; mt < 2; ++mt)
#pragma unroll
                for (int nt = 0; nt < 8; ++nt)
                    mma16(acc[mt][nt], af[mt][0], af[mt][1], af[mt][2], af[mt][3],
                          bfr[nt][0], bfr[nt][1]);
        }
    }

    // epilogue: silu(gate)*up -> silu16
#pragma unroll
    for (int mt = 0; mt < 2; ++mt) {
        const int r0 = bm + wm + mt * 16 + grp;
#pragma unroll
        for (int nt = 0; nt < 4; ++nt) {
            const int c = bn + wn2 + nt * 8 + 2 * qd;
            float s0[4];
#pragma unroll
            for (int j = 0; j < 4; ++j) {
                const float g = acc[mt][nt][j];
                s0[j] = __fdividef(g, 1.0f + ex2(-g * LOG2E)) * acc[mt][nt + 4][j];
            }
            *(uint32_t*)&g_silu16[(size_t)r0 * D_FF + c] = pkbf(s0[0], s0[1]);
            *(uint32_t*)&g_silu16[(size_t)(r0 + 8) * D_FF + c] = pkbf(s0[2], s0[3]);
        }
    }
}

// -------------------- flash attention: paired q-tiles, quad-buffer KV --------
// Grid (16,4,4): block does q-tile x (x+1 ktiles) then 31-x (32-x ktiles) = 33.
// One sync per 2 key-tiles. Q pre-scaled by 0.125*log2e.
__global__ void __launch_bounds__(128, 3) flash_kernel() {
    extern __shared__ uint32_t fsm[];
    uint32_t* Qs = fsm;                       // 2048 words (8KB)
    const uint32_t qsb = s2u(Qs);
    const uint32_t ksb = qsb + 8192;          // 4 x 8KB
    const uint32_t vsb = ksb + 32768;         // 4 x 8KB
    const int xpair = blockIdx.x, h = blockIdx.y, b = blockIdx.z;
    const int tid = threadIdx.x, lane = tid & 31, w = tid >> 5;
    const int m4 = lane >> 3, r8 = lane & 7;
    const int grp = lane >> 2, qd = lane & 3;
    const size_t tok = (size_t)b * T_;
    const int bh = b * 4 + h;
    const bf16* Kg = g_k16 + tok * D_MODEL + h * 64;
    const bf16* Vg = g_vt16 + (size_t)bh * 64 * T_;
    const int khalf = m4 >> 1;

    uint32_t co4[4];
#pragma unroll
    for (int kb = 0; kb < 4; ++kb) co4[kb] = (uint32_t)(((kb * 2 + khalf) ^ r8) << 4);

    const uint32_t aQ = qsb + (uint32_t)((w * 16 + (m4 & 1) * 8 + r8) * 128);
    int rowKV[4];
#pragma unroll
    for (int g = 0; g < 4; ++g) rowKV[g] = ((2 * g + (m4 & 1)) * 8 + r8) * 128;

    const int pr = tid >> 3, pc = tid & 7;
    const uint32_t so0 = (uint32_t)((pr * 32 + ((pc ^ (pr & 7)) << 2)) << 2);
    const bf16* kbase = Kg + (size_t)pr * D_MODEL + pc * 8;
    const bf16* vbase = Vg + (size_t)pr * T_ + pc * 8;

    for (int rep = 0; rep < 2; ++rep) {
        const int qbi = rep ? (31 - xpair) : xpair;
        const int q0 = qbi * 64;
        const int qw = q0 + w * 16;
        const bf16* Qg = g_q16 + (tok + q0) * D_MODEL + h * 64;
        const int ntiles = qbi + 1;

        __syncthreads();  // all warps done with prior rep's buffers + Qs

        // issue tiles 0 (buf0) and 1 (buf1)
#pragma unroll
        for (int i = 0; i < 4; ++i) {
            cp16(ksb + so0 + i * 2048, kbase + (size_t)i * 16 * D_MODEL);
            cp16(vsb + so0 + i * 2048, vbase + (size_t)i * 16 * T_);
        }
        CP_COMMIT;
        if (ntiles > 1) {
            const bf16* kp = kbase + (size_t)64 * D_MODEL;
            const bf16* vp = vbase + 64;
#pragma unroll
            for (int i = 0; i < 4; ++i) {
                cp16(ksb + 8192 + so0 + i * 2048, kp + (size_t)i * 16 * D_MODEL);
                cp16(vsb + 8192 + so0 + i * 2048, vp + (size_t)i * 16 * T_);
            }
            CP_COMMIT;
        }

        // load Q tile
#pragma unroll
        for (int i = 0; i < 4; ++i) {
            const int idx = tid + i * 128;
            const int r = idx >> 3, c = idx & 7;
            const uint4 v = *(const uint4*)(Qg + (size_t)r * D_MODEL + c * 8);
            *(uint4*)&Qs[r * 32 + ((c ^ (r & 7)) << 2)] = v;
        }

        float o[8][4];
        float li0 = 0.f, li1 = 0.f;
#pragma unroll
        for (int nt = 0; nt < 8; nt++)
#pragma unroll
            for (int j = 0; j < 4; j++) o[nt][j] = 0.f;

        const int npairs = (ntiles + 1) >> 1;
        for (int pt = 0; pt < npairs; ++pt) {
            const int kt0 = 2 * pt;
            CP_WAIT0;
            __syncthreads();
            // prefetch tiles kt0+2, kt0+3
#pragma unroll
            for (int pf = 2; pf < 4; ++pf) {
                const int ktp = kt0 + pf;
                if (ktp < ntiles) {
                    const uint32_t bo = (uint32_t)(ktp & 3) * 8192;
                    const bf16* kp = kbase + (size_t)(ktp * 64) * D_MODEL;
                    const bf16* vp = vbase + ktp * 64;
#pragma unroll
                    for (int i = 0; i < 4; ++i) {
                        cp16(ksb + bo + so0 + i * 2048, kp + (size_t)i * 16 * D_MODEL);
                        cp16(vsb + bo + so0 + i * 2048, vp + (size_t)i * 16 * T_);
                    }
                    CP_COMMIT;
                }
            }
            // process tiles kt0 and kt0+1
#pragma unroll
            for (int sub = 0; sub < 2; ++sub) {
                const int kt = kt0 + sub;
                if (kt >= ntiles) break;
                const int k0 = kt * 64;
                const uint32_t Kb = ksb + (uint32_t)(kt & 3) * 8192;
                const uint32_t Vb = vsb + (uint32_t)(kt & 3) * 8192;

                float s[8][4];
#pragma unroll
                for (int nt = 0; nt < 8; nt++)
#pragma unroll
                    for (int j = 0; j < 4; j++) s[nt][j] = 0.f;
#pragma unroll
                for (int kb = 0; kb < 4; ++kb) {
                    uint32_t a0, a1, a2, a3;
                    ldsm4(a0, a1, a2, a3, aQ + co4[kb]);
                    uint32_t kf[8][2];
#pragma unroll
                    for (int g = 0; g < 4; ++g) {
                        uint32_t b0, b1, b2, b3;
                        ldsm4(b0, b1, b2, b3, Kb + rowKV[g] + co4[kb]);
                        kf[2 * g][0] = b0; kf[2 * g + 1][0] = b1;
                        kf[2 * g][1] = b2; kf[2 * g + 1][1] = b3;
                    }
#pragma unroll
                    for (int nt = 0; nt < 8; ++nt)
                        mma16(s[nt], a0, a1, a2, a3, kf[nt][0], kf[nt][1]);
                }

                const int r0 = qw + grp, r1 = r0 + 8;
                const bool diag = (k0 + 63 > qw);
                float sum0 = 0.f, sum1 = 0.f;
#pragma unroll
                for (int nt = 0; nt < 8; nt++) {
                    float v0 = s[nt][0], v1 = s[nt][1], v2 = s[nt][2], v3 = s[nt][3];
                    if (diag) {
                        const int c0 = k0 + nt * 8 + 2 * qd;
                        if (c0 > r0) v0 = -1e30f;
                        if (c0 + 1 > r0) v1 = -1e30f;
                        if (c0 > r1) v2 = -1e30f;
                        if (c0 + 1 > r1) v3 = -1e30f;
                    }
                    s[nt][0] = ex2(v0);
                    s[nt][1] = ex2(v1);
                    s[nt][2] = ex2(v2);
                    s[nt][3] = ex2(v3);
                    sum0 += s[nt][0] + s[nt][1];
                    sum1 += s[nt][2] + s[nt][3];
                }
                li0 += sum0;
                li1 += sum1;

                uint32_t pa[4][4];
#pragma unroll
                for (int ks = 0; ks < 4; ++ks) {
                    pa[ks][0] = pkbf(s[2 * ks][0], s[2 * ks][1]);
                    pa[ks][1] = pkbf(s[2 * ks][2], s[2 * ks][3]);
                    pa[ks][2] = pkbf(s[2 * ks + 1][0], s[2 * ks + 1][1]);
                    pa[ks][3] = pkbf(s[2 * ks + 1][2], s[2 * ks + 1][3]);
                }

#pragma unroll
                for (int ks = 0; ks < 4; ++ks) {
                    uint32_t vf[8][2];
#pragma unroll
                    for (int g = 0; g < 4; ++g) {
                        uint32_t b0, b1, b2, b3;
                        ldsm4(b0, b1, b2, b3, Vb + rowKV[g] + co4[ks]);
                        vf[2 * g][0] = b0; vf[2 * g + 1][0] = b1;
                        vf[2 * g][1] = b2; vf[2 * g + 1][1] = b3;
                    }
#pragma unroll
                    for (int nt = 0; nt < 8; ++nt)
                        mma16(o[nt], pa[ks][0], pa[ks][1], pa[ks][2], pa[ks][3],
                              vf[nt][0], vf[nt][1]);
                }
            }
        }

        li0 += __shfl_xor_sync(0xffffffffu, li0, 1);
        li0 += __shfl_xor_sync(0xffffffffu, li0, 2);
        li1 += __shfl_xor_sync(0xffffffffu, li1, 1);
        li1 += __shfl_xor_sync(0xffffffffu, li1, 2);

        const float inv0 = 1.0f / li0, inv1 = 1.0f / li1;
        const int r0 = qw + grp;
#pragma unroll
        for (int nt = 0; nt < 8; ++nt) {
            const int c = h * 64 + nt * 8 + 2 * qd;
            *(uint32_t*)&g_attn16[(tok + r0) * D_MODEL + c] = pkbf(o[nt][0] * inv0, o[nt][1] * inv0);
            *(uint32_t*)&g_attn16[(tok + r0 + 8) * D_MODEL + c] = pkbf(o[nt][2] * inv1, o[nt][3] * inv1);
        }
    }
}

// -------------------- launch --------------------
extern "C" void kernel_launch(void* const* d_in, const int* in_sizes, int n_in,
                              void* d_out, int out_size) {
    const float* x          = (const float*)d_in[0];
    const float* rms_attn_w = (const float*)d_in[2];
    const float* wq         = (const float*)d_in[3];
    const float* wk         = (const float*)d_in[4];
    const float* wv         = (const float*)d_in[5];
    const float* wo         = (const float*)d_in[6];
    const float* rms_ffn_w  = (const float*)d_in[7];
    const float* wg         = (const float*)d_in[8];
    const float* wu         = (const float*)d_in[9];
    const float* wd         = (const float*)d_in[10];
    float* out = (float*)d_out;

    bf16 *w16, *attn16, *silu16;
    float* x1;
    cudaGetSymbolAddress((void**)&w16, g_w16);
    cudaGetSymbolAddress((void**)&attn16, g_attn16);
    cudaGetSymbolAddress((void**)&silu16, g_silu16);
    cudaGetSymbolAddress((void**)&x1, g_x1);

    const int FLASH_SMEM = (2048 + 4 * 2048 + 4 * 2048) * 4;           // 73728
    const int WONORM_SMEM = (3 * 1024 + 3 * 4096) * 4 + (64 + 256) * 4; // 62720
    cudaFuncSetAttribute(flash_kernel, cudaFuncAttributeMaxDynamicSharedMemorySize, FLASH_SMEM);
    cudaFuncSetAttribute(wo_norm_kernel, cudaFuncAttributeMaxDynamicSharedMemorySize, WONORM_SMEM);

    // 1. convert weights to bf16
    cvtw_kernel<<<dim3(256, 7), 256>>>(wq, wk, wv, wo, wg, wu, wd);
    // 2. h16 = rmsnorm(x)
    rmsnorm_kernel<<<BT, 256>>>(x, rms_attn_w);
    // 3. q(scaled),k,vt
    qkv_kernel<<<dim3(BT / 64, 2, 3), 128>>>();
    // 4. attention (balanced causal pairs, quad-buffer)
    flash_kernel<<<dim3(16, 4, B_), 128, FLASH_SMEM>>>();
    // 5. x1 = x + attn @ wo^T; h16 = rmsnorm(x1)  (fused)
    wo_norm_kernel<<<BT / 64, 256, WONORM_SMEM>>>(attn16, w16 + 196608, x, rms_ffn_w, x1);
    // 6. silu16 = silu(h16@wg^T) * (h16@wu^T)
    gateup_kernel<<<dim3(BT / 64, D_FF / 64), 128>>>();
    // 7. out = x1 + silu16 @ wd^T
    out_gemm_kernel<<<dim3(BT / 64, 2), 128>>>(silu16, w16 + 786432, x1, out, D_FF);
}